// round 4
// baseline (speedup 1.0000x reference)
#include <cuda_runtime.h>
#include <cuda_fp16.h>
#include <math.h>

// x = (4, 64, 128, 128) fp32, K=7 -> out (4, 49, 16384) fp32
#define BATCH   4
#define CHN     64
#define HT      128
#define WD      128
#define HW      (HT * WD)            // 16384
#define KW      7
#define PADR    3
#define TILEH   32
#define TILEW   16
#define TRH     (TILEH + 2 * PADR)   // 38
#define TRW     (TILEW + 2 * PADR)   // 22
#define NPIX    (TRH * TRW)          // 836
#define NTHREADS 512                 // one center pixel per thread -> 16 warps/SM
#define NOFF    (KW * KW)            // 49
#define EPSV    1e-7f

// smem: fp16 tile [NPIX][64ch] chunk-swizzled (8 chunks of 8 halves) + fp32 norms
#define TILE_HALVES  (NPIX * 64)
#define SMEM_BYTES   (TILE_HALVES * 2 + NPIX * 4)   // 107008 + 3344 = 110,352 B

__global__ __launch_bounds__(NTHREADS, 1)
void region_sim_kernel(const float* __restrict__ x, float* __restrict__ out) {
    extern __shared__ __align__(16) char smem_raw[];
    __half* tile  = (__half*)smem_raw;                   // [NPIX][64], swizzled
    float*  norms = (float*)(smem_raw + TILE_HALVES * 2);

    const int b   = blockIdx.z;
    const int w0  = blockIdx.x * TILEW;
    const int h0  = blockIdx.y * TILEH;
    const int tid = threadIdx.x;

    // ---- Phase 1: gmem fp32 -> fp16 smem tile, 16B chunk per (pixel, q), XOR swizzle ----
    const float* xb = x + (size_t)b * CHN * HW;
#pragma unroll 1
    for (int p = tid; p < NPIX; p += NTHREADS) {
        int r   = p / TRW;
        int col = p - r * TRW;
        int gh  = h0 - PADR + r;
        int gw  = w0 - PADR + col;
        const bool inb = (gh >= 0 && gh < HT && gw >= 0 && gw < WD);
        const int gi = gh * WD + gw;
        __half2* tp = (__half2*)(tile + p * 64);
        const int sw = p & 7;
#pragma unroll 1
        for (int q = 0; q < 8; q++) {                    // 8 channels per chunk
            __half2 h0v = __float2half2_rn(0.f), h1v = h0v, h2v = h0v, h3v = h0v;
            if (inb) {
                const float* x0 = xb + (size_t)(q * 8) * HW + gi;
                h0v = __floats2half2_rn(x0[0],      x0[HW]);
                h1v = __floats2half2_rn(x0[2 * HW], x0[3 * HW]);
                h2v = __floats2half2_rn(x0[4 * HW], x0[5 * HW]);
                h3v = __floats2half2_rn(x0[6 * HW], x0[7 * HW]);
            }
            __half2* dst = tp + (size_t)(q ^ sw) * 4;    // 16B-aligned chunk
            dst[0] = h0v; dst[1] = h1v; dst[2] = h2v; dst[3] = h3v;
        }
    }
    __syncthreads();

    // ---- Phase 2: fp32 norms computed FROM the fp16 values (consistent cosine) ----
#pragma unroll 1
    for (int p = tid; p < NPIX; p += NTHREADS) {
        const uint4* tp = (const uint4*)(tile + p * 64);
        const int sw = p & 7;
        float4 s = make_float4(0.f, 0.f, 0.f, 0.f);
#pragma unroll
        for (int q = 0; q < 8; q++) {
            uint4 hv = tp[q ^ sw];
            float2 f0 = __half22float2(*(__half2*)&hv.x);
            float2 f1 = __half22float2(*(__half2*)&hv.y);
            float2 f2 = __half22float2(*(__half2*)&hv.z);
            float2 f3 = __half22float2(*(__half2*)&hv.w);
            s.x += f0.x * f0.x + f2.x * f2.x;
            s.y += f0.y * f0.y + f2.y * f2.y;
            s.z += f1.x * f1.x + f3.x * f3.x;
            s.w += f1.y * f1.y + f3.y * f3.y;
        }
        norms[p] = sqrtf((s.x + s.y) + (s.z + s.w));
    }
    __syncthreads();

    // ---- Phase 3: one center per thread, fp32 center regs, fp16 neighbor stream ----
    const int lw = tid & (TILEW - 1);      // 0..15
    const int lh = tid >> 4;               // 0..31
    const int colC = PADR + lw;
    const int rC   = PADR + lh;
    const int pC   = rC * TRW + colC;

    float4 cen[16];                        // 64 fp32 channels
    {
        const uint4* cp = (const uint4*)(tile + pC * 64);
        const int sw = pC & 7;
#pragma unroll
        for (int q = 0; q < 8; q++) {
            uint4 hv = cp[q ^ sw];
            float2 f0 = __half22float2(*(__half2*)&hv.x);
            float2 f1 = __half22float2(*(__half2*)&hv.y);
            float2 f2 = __half22float2(*(__half2*)&hv.z);
            float2 f3 = __half22float2(*(__half2*)&hv.w);
            cen[2 * q]     = make_float4(f0.x, f0.y, f1.x, f1.y);
            cen[2 * q + 1] = make_float4(f2.x, f2.y, f3.x, f3.y);
        }
    }
    const float nc = norms[pC];

    float den = 0.f;
    const size_t obase = (size_t)b * NOFF * HW + (size_t)(h0 + lh) * WD + (w0 + lw);

#pragma unroll 1
    for (int o = -PADR; o <= PADR; o++) {
#pragma unroll 1
        for (int dj = -PADR; dj <= PADR; dj++) {
            const int pn = (rC + o) * TRW + colC + dj;
            const uint4* nb = (const uint4*)(tile + pn * 64);
            const int sw = pn & 7;
            float4 a = make_float4(0.f, 0.f, 0.f, 0.f);
#pragma unroll
            for (int q = 0; q < 8; q++) {
                uint4 hv = nb[q ^ sw];
                float2 f0 = __half22float2(*(__half2*)&hv.x);
                float2 f1 = __half22float2(*(__half2*)&hv.y);
                float2 f2 = __half22float2(*(__half2*)&hv.z);
                float2 f3 = __half22float2(*(__half2*)&hv.w);
                a.x += cen[2 * q].x * f0.x + cen[2 * q + 1].x * f2.x;
                a.y += cen[2 * q].y * f0.y + cen[2 * q + 1].y * f2.y;
                a.z += cen[2 * q].z * f1.x + cen[2 * q + 1].z * f3.x;
                a.w += cen[2 * q].w * f1.y + cen[2 * q + 1].w * f3.y;
            }
            float dot = (a.x + a.y) + (a.z + a.w);
            float e = __expf(__fdividef(dot, nc * norms[pn] + EPSV)); // sim in [-1,1]
            den += e;
            int kk = (o + PADR) * KW + (dj + PADR);
            out[obase + (size_t)kk * HW] = e;
        }
    }

    // ---- Phase 4: normalize in-place, 7-wide batches (MLP=7, L2-resident) ----
    const float ri = __fdividef(1.f, den);
#pragma unroll 1
    for (int g = 0; g < 7; g++) {
        float v[7];
#pragma unroll
        for (int j = 0; j < 7; j++)
            v[j] = out[obase + (size_t)(g * 7 + j) * HW];
#pragma unroll
        for (int j = 0; j < 7; j++)
            out[obase + (size_t)(g * 7 + j) * HW] = v[j] * ri;
    }
}

extern "C" void kernel_launch(void* const* d_in, const int* in_sizes, int n_in,
                              void* d_out, int out_size) {
    (void)in_sizes; (void)n_in; (void)out_size;
    const float* x = (const float*)d_in[0];
    float* out = (float*)d_out;

    cudaFuncSetAttribute(region_sim_kernel,
                         cudaFuncAttributeMaxDynamicSharedMemorySize, SMEM_BYTES);

    dim3 grid(WD / TILEW, HT / TILEH, BATCH);   // 8 x 4 x 4 = 128 blocks = 1 wave
    region_sim_kernel<<<grid, NTHREADS, SMEM_BYTES>>>(x, out);
}

// round 5
// speedup vs baseline: 1.6505x; 1.6505x over previous
#include <cuda_runtime.h>
#include <cuda_fp16.h>
#include <math.h>

// x = (4, 64, 128, 128) fp32, K=7 -> out (4, 49, 16384) fp32
#define BATCH   4
#define CHN     64
#define HT      128
#define WD      128
#define HW      (HT * WD)            // 16384
#define KW      7
#define PADR    3
#define TILEH   32
#define TILEW   16
#define TRH     (TILEH + 2 * PADR)   // 38
#define TRW     (TILEW + 2 * PADR)   // 22
#define NPIX    (TRH * TRW)          // 836
#define NTHREADS 512                 // one center per thread, 16 warps/SM
#define NOFF    (KW * KW)            // 49
#define EPSV    1e-7f

// smem: fp16 tile [NPIX][64ch] chunk-swizzled (8 chunks of 8 halves) + fp32 norms
#define TILE_HALVES  (NPIX * 64)
#define SMEM_BYTES   (TILE_HALVES * 2 + NPIX * 4)   // 110,352 B

__global__ __launch_bounds__(NTHREADS, 1)
void region_sim_kernel(const float* __restrict__ x, float* __restrict__ out) {
    extern __shared__ __align__(16) char smem_raw[];
    __half* tile  = (__half*)smem_raw;                   // [NPIX][64], swizzled
    float*  norms = (float*)(smem_raw + TILE_HALVES * 2);

    const int b   = blockIdx.z;
    const int w0  = blockIdx.x * TILEW;
    const int h0  = blockIdx.y * TILEH;
    const int tid = threadIdx.x;

    // ---- Phase 1: gmem fp32 -> fp16 smem tile, 16B chunk per (pixel, q), XOR swizzle ----
    const float* xb = x + (size_t)b * CHN * HW;
#pragma unroll 1
    for (int p = tid; p < NPIX; p += NTHREADS) {
        int r   = p / TRW;
        int col = p - r * TRW;
        int gh  = h0 - PADR + r;
        int gw  = w0 - PADR + col;
        const bool inb = (gh >= 0 && gh < HT && gw >= 0 && gw < WD);
        const int gi = gh * WD + gw;
        __half2* tp = (__half2*)(tile + p * 64);
        const int sw = p & 7;
#pragma unroll 1
        for (int q = 0; q < 8; q++) {                    // 8 channels per chunk
            __half2 h0v = __float2half2_rn(0.f), h1v = h0v, h2v = h0v, h3v = h0v;
            if (inb) {
                const float* x0 = xb + (size_t)(q * 8) * HW + gi;
                h0v = __floats2half2_rn(x0[0],      x0[HW]);
                h1v = __floats2half2_rn(x0[2 * HW], x0[3 * HW]);
                h2v = __floats2half2_rn(x0[4 * HW], x0[5 * HW]);
                h3v = __floats2half2_rn(x0[6 * HW], x0[7 * HW]);
            }
            __half2* dst = tp + (size_t)(q ^ sw) * 4;    // 16B-aligned chunk
            dst[0] = h0v; dst[1] = h1v; dst[2] = h2v; dst[3] = h3v;
        }
    }
    __syncthreads();

    // ---- Phase 2: fp32 norms computed FROM the fp16 values (consistent cosine) ----
#pragma unroll 1
    for (int p = tid; p < NPIX; p += NTHREADS) {
        const uint4* tp = (const uint4*)(tile + p * 64);
        const int sw = p & 7;
        float4 s = make_float4(0.f, 0.f, 0.f, 0.f);
#pragma unroll
        for (int q = 0; q < 8; q++) {
            uint4 hv = tp[q ^ sw];
            float2 f0 = __half22float2(*(__half2*)&hv.x);
            float2 f1 = __half22float2(*(__half2*)&hv.y);
            float2 f2 = __half22float2(*(__half2*)&hv.z);
            float2 f3 = __half22float2(*(__half2*)&hv.w);
            s.x += f0.x * f0.x + f2.x * f2.x;
            s.y += f0.y * f0.y + f2.y * f2.y;
            s.z += f1.x * f1.x + f3.x * f3.x;
            s.w += f1.y * f1.y + f3.y * f3.y;
        }
        norms[p] = sqrtf((s.x + s.y) + (s.z + s.w));
    }
    __syncthreads();

    // ---- Phase 3: center kept as 32 half2 regs; dot via HFMA2 (4 accs, chains of 8) ----
    const int lw = tid & (TILEW - 1);      // 0..15
    const int lh = tid >> 4;               // 0..31
    const int colC = PADR + lw;
    const int rC   = PADR + lh;
    const int pC   = rC * TRW + colC;

    __half2 cen[32];                       // chunk q -> cen[4q..4q+3]
    {
        const uint4* cp = (const uint4*)(tile + pC * 64);
        const int sw = pC & 7;
#pragma unroll
        for (int q = 0; q < 8; q++) {
            uint4 hv = cp[q ^ sw];
            cen[4 * q + 0] = *(__half2*)&hv.x;
            cen[4 * q + 1] = *(__half2*)&hv.y;
            cen[4 * q + 2] = *(__half2*)&hv.z;
            cen[4 * q + 3] = *(__half2*)&hv.w;
        }
    }
    const float nc = norms[pC];

    float den = 0.f;
    const size_t obase = (size_t)b * NOFF * HW + (size_t)(h0 + lh) * WD + (w0 + lw);
    const __half2 hz = __float2half2_rn(0.f);

#pragma unroll 1
    for (int o = -PADR; o <= PADR; o++) {
        const int pbase = (rC + o) * TRW + colC;
#pragma unroll
        for (int dj = -PADR; dj <= PADR; dj++) {   // fully unrolled: 7 chains in flight
            const int pn = pbase + dj;
            const uint4* nb = (const uint4*)(tile + pn * 64);
            const int sw = pn & 7;
            __half2 a0 = hz, a1 = hz, a2 = hz, a3 = hz;
#pragma unroll
            for (int q = 0; q < 8; q++) {
                uint4 hv = nb[q ^ sw];
                a0 = __hfma2(cen[4 * q + 0], *(__half2*)&hv.x, a0);
                a1 = __hfma2(cen[4 * q + 1], *(__half2*)&hv.y, a1);
                a2 = __hfma2(cen[4 * q + 2], *(__half2*)&hv.z, a2);
                a3 = __hfma2(cen[4 * q + 3], *(__half2*)&hv.w, a3);
            }
            float2 f0 = __half22float2(a0);
            float2 f1 = __half22float2(a1);
            float2 f2 = __half22float2(a2);
            float2 f3 = __half22float2(a3);
            float dot = ((f0.x + f0.y) + (f1.x + f1.y))
                      + ((f2.x + f2.y) + (f3.x + f3.y));
            float e = __expf(__fdividef(dot, nc * norms[pn] + EPSV)); // sim in [-1,1]
            den += e;
            int kk = (o + PADR) * KW + (dj + PADR);
            out[obase + (size_t)kk * HW] = e;
        }
    }

    // ---- Phase 4: normalize in-place, 7-wide batches (MLP=7, L2-resident) ----
    const float ri = __fdividef(1.f, den);
#pragma unroll 1
    for (int g = 0; g < 7; g++) {
        float v[7];
#pragma unroll
        for (int j = 0; j < 7; j++)
            v[j] = out[obase + (size_t)(g * 7 + j) * HW];
#pragma unroll
        for (int j = 0; j < 7; j++)
            out[obase + (size_t)(g * 7 + j) * HW] = v[j] * ri;
    }
}

extern "C" void kernel_launch(void* const* d_in, const int* in_sizes, int n_in,
                              void* d_out, int out_size) {
    (void)in_sizes; (void)n_in; (void)out_size;
    const float* x = (const float*)d_in[0];
    float* out = (float*)d_out;

    cudaFuncSetAttribute(region_sim_kernel,
                         cudaFuncAttributeMaxDynamicSharedMemorySize, SMEM_BYTES);

    dim3 grid(WD / TILEW, HT / TILEH, BATCH);   // 8 x 4 x 4 = 128 blocks = 1 wave
    region_sim_kernel<<<grid, NTHREADS, SMEM_BYTES>>>(x, out);
}